// round 16
// baseline (speedup 1.0000x reference)
#include <cuda_runtime.h>
#include <cuda_fp16.h>

#define NN   8
#define CC   256
#define HC   128          // channels per half-block
#define HH   128
#define WW   128
#define HWSZ 16384
#define NBOX 20
#define TEMP     0.5f
#define INVTEMP  2.0f
#define ALPHA    1e-3f
#define BETA     5e-4f
#define GAMMA    1e-3f
#define LAMB     5e-6f
#define IMGF     1024.0f
#define LN_EPS   1e-5f

#define SM_SC  16384.0f
#define FG_SC  64.0f
#define BG_SC  16384.0f

// ---------------- scratch ----------------
__device__ float4 g_pp [NN * HWSZ];   // combined (fs, ft, cs, ct) per pixel
__device__ float  g_mfg[NN * HWSZ];
__device__ uint2  g_smwh[NN * HWSZ];  // packed fp16 weights
__device__ float g_ch_s [NN * CC];
__device__ float g_ch_t [NN * CC];
__device__ float g_ctx_s[NN * CC];
__device__ float g_ctx_t[NN * CC];
__device__ float g_rowd [NN * CC];
__device__ float g_fgrow[NN * CC];
__device__ float g_bgrow[NN * CC];
__device__ float g_denp[NN][5][32];   // per-block partials: s0,s1,s2,s3,bg
__device__ float g_fgsum, g_bgsum, g_d2sum, g_maskloss;
__device__ float g_accx, g_accd;

// ---------------- helpers ----------------
__device__ __forceinline__ float warpsum(float v) {
#pragma unroll
    for (int o = 16; o > 0; o >>= 1) v += __shfl_xor_sync(0xffffffffu, v, o);
    return v;
}
__device__ __forceinline__ float blocksum(float v, float* sbuf) {
    int tid = threadIdx.x, lane = tid & 31, warp = tid >> 5;
    int nw = blockDim.x >> 5;
    v = warpsum(v);
    if (lane == 0) sbuf[warp] = v;
    __syncthreads();
    if (warp == 0) {
        float r = (lane < nw) ? sbuf[lane] : 0.0f;
        r = warpsum(r);
        if (lane == 0) sbuf[0] = r;
    }
    __syncthreads();
    float r = sbuf[0];
    __syncthreads();
    return r;
}
__device__ __forceinline__ float2 h2f(unsigned u) {
    __half2 h = *reinterpret_cast<__half2*>(&u);
    return __half22float2(h);
}

// ---------------- pass1: mask + per-pixel sums + denominators (fused) --------
// grid (32, NN), block 512: lower half = channels 0..127, upper = 128..255
__global__ void __launch_bounds__(512) k_pass1(
        const float* __restrict__ S, const float* __restrict__ T,
        const float* __restrict__ wms, const float* __restrict__ wmt,
        const float* __restrict__ gt) {
    __shared__ float sws[CC], swt[CC];
    __shared__ float bhmin[NBOX], bhmax[NBOX], bwmin[NBOX], bwmax[NBOX], barea[NBOX];
    __shared__ float4 xch0[256], xch1[256];   // upper-half partials (pixel 0 / 1)
    __shared__ float sbuf[32];
    int tid = threadIdx.x;
    int n = blockIdx.y;
    int half = tid >> 8;      // 0 or 1
    int lt = tid & 255;
    int c0 = half * HC;

    if (blockIdx.x == 0 && n == 0 && tid == 0) {
        g_fgsum = 0.f; g_bgsum = 0.f; g_d2sum = 0.f; g_maskloss = 0.f;
        g_accx = 0.f; g_accd = 0.f;
    }
    if (tid < CC) { sws[tid] = wms[tid]; swt[tid] = wmt[tid]; }
    if (tid < NBOX) {
        const float* b = gt + ((size_t)n * NBOX + tid) * 4;
        float wmin = floorf(b[0] * ((float)WW / IMGF));
        float hmin = floorf(b[1] * ((float)HH / IMGF));
        float wmax = ceilf (b[2] * ((float)WW / IMGF));
        float hmax = ceilf (b[3] * ((float)HH / IMGF));
        bhmin[tid] = hmin; bhmax[tid] = hmax;
        bwmin[tid] = wmin; bwmax[tid] = wmax;
        barea[tid] = 1.0f / ((hmax + 1.0f - hmin) * (wmax + 1.0f - wmin));
    }
    __syncthreads();

    int p = blockIdx.x * 512 + lt * 2;
    int o = n * HWSZ + p;

    const float2* Sp = (const float2*)(S + ((size_t)n * CC + c0) * HWSZ + p);
    const float2* Tp = (const float2*)(T + ((size_t)n * CC + c0) * HWSZ + p);
    float2 fs = make_float2(0.f, 0.f), ft = fs, cs = fs, ct = fs;
#pragma unroll 1
    for (int cg = 0; cg < HC; cg += 8) {
        float2 sv[8], tv[8];
#pragma unroll
        for (int u = 0; u < 8; u++) {
            sv[u] = Sp[(size_t)(cg + u) * (HWSZ / 2)];
            tv[u] = Tp[(size_t)(cg + u) * (HWSZ / 2)];
        }
#pragma unroll
        for (int u = 0; u < 8; u++) {
            float2 s = sv[u], t = tv[u];
            fs.x += fabsf(s.x); fs.y += fabsf(s.y);
            ft.x += fabsf(t.x); ft.y += fabsf(t.y);
            float ws = sws[c0 + cg + u], wt = swt[c0 + cg + u];
            cs.x = fmaf(s.x, ws, cs.x); cs.y = fmaf(s.y, ws, cs.y);
            ct.x = fmaf(t.x, wt, ct.x); ct.y = fmaf(t.y, wt, ct.y);
        }
    }
    if (half == 1) {
        xch0[lt] = make_float4(fs.x, ft.x, cs.x, ct.x);
        xch1[lt] = make_float4(fs.y, ft.y, cs.y, ct.y);
    }
    __syncthreads();

    float s0 = 0.f, s1 = 0.f, s2 = 0.f, s3 = 0.f, bgp = 0.f;
    if (half == 0) {
        float4 u0 = xch0[lt], u1 = xch1[lt];
        float fs0 = fs.x + u0.x, ft0 = ft.x + u0.y, cs0 = cs.x + u0.z, ct0 = ct.x + u0.w;
        float fs1 = fs.y + u1.x, ft1 = ft.y + u1.y, cs1 = cs.y + u1.z, ct1 = ct.y + u1.w;

        float h0 = (float)(p >> 7), w0 = (float)(p & 127);
        float h1 = (float)((p + 1) >> 7), w1 = (float)((p + 1) & 127);
        float mfg0 = 0.f, mfg1 = 0.f;
#pragma unroll 1
        for (int b = 0; b < NBOX; b++) {
            float hm = bhmin[b], hM = bhmax[b], wm = bwmin[b], wM = bwmax[b], ar = barea[b];
            if (h0 >= hm && h0 <= hM && w0 >= wm && w0 <= wM) mfg0 = fmaxf(mfg0, ar);
            if (h1 >= hm && h1 <= hM && w1 >= wm && w1 <= wM) mfg1 = fmaxf(mfg1, ar);
        }
        g_mfg[o] = mfg0; g_mfg[o + 1] = mfg1;
        g_pp[o]     = make_float4(fs0, ft0, cs0, ct0);
        g_pp[o + 1] = make_float4(fs1, ft1, cs1, ct1);

        const float sc = INVTEMP / (float)CC;
        s0 = __expf(fs0 * sc) + __expf(fs1 * sc);
        s1 = __expf(ft0 * sc) + __expf(ft1 * sc);
        s2 = __expf(cs0) + __expf(cs1);
        s3 = __expf(ct0) + __expf(ct1);
        bgp = (mfg0 == 0.f ? 1.f : 0.f) + (mfg1 == 0.f ? 1.f : 0.f);
    }
    s0 = blocksum(s0, sbuf); s1 = blocksum(s1, sbuf);
    s2 = blocksum(s2, sbuf); s3 = blocksum(s3, sbuf);
    bgp = blocksum(bgp, sbuf);
    if (tid == 0) {
        g_denp[n][0][blockIdx.x] = s0;
        g_denp[n][1][blockIdx.x] = s1;
        g_denp[n][2][blockIdx.x] = s2;
        g_denp[n][3][blockIdx.x] = s3;
        g_denp[n][4][blockIdx.x] = bgp;
    }
}

// ---------------- k_wgt: fp16-packed weights + |Ss-St| term ------------------
// grid (64, NN), block 256; reduces the 32 denominator partials in warp 0
__global__ void __launch_bounds__(256) k_wgt() {
    __shared__ float sbuf[32];
    __shared__ float sden[5];
    int n = blockIdx.y, tid = threadIdx.x;
    int lane = tid & 31, warp = tid >> 5;
    if (warp == 0) {
#pragma unroll
        for (int j = 0; j < 5; j++) {
            float v = warpsum(g_denp[n][j][lane]);
            if (lane == 0) sden[j] = v;
        }
    }
    __syncthreads();
    int o = n * HWSZ + blockIdx.x * 256 + tid;
    const float sc = INVTEMP / (float)CC;
    float r0 = 1.0f / sden[0];
    float r1 = 1.0f / sden[1];
    float r2 = 1.0f / sden[2];
    float r3 = 1.0f / sden[3];
    float bgc = sden[4];
    float invbg = (bgc > 0.f) ? (1.0f / bgc) : 0.f;
    float4 a = g_pp[o];
    float mfg = g_mfg[o];
    float Ss  = (float)HWSZ * __expf(a.x * sc) * r0;
    float St  = (float)HWSZ * __expf(a.y * sc) * r1;
    float sms = __expf(a.z) * r2;
    float smt = __expf(a.w) * r3;
    float mbg = (mfg > 0.f) ? 0.f : invbg;
    __half2 hA = __floats2half2_rn(sms * SM_SC, smt * SM_SC);
    __half2 hB = __floats2half2_rn(St * mfg * FG_SC, St * mbg * BG_SC);
    uint2 v;
    v.x = *reinterpret_cast<unsigned*>(&hA);
    v.y = *reinterpret_cast<unsigned*>(&hB);
    g_smwh[o] = v;
    float sd = blocksum(fabsf(Ss - St), sbuf);
    if (tid == 0) atomicAdd(&g_maskloss, sd);
}

// ---------------- k_rowk: second stream -> all per-channel reductions --------
// grid (CC/2, NN), block 256, 2 channels/block, fp16 weights
__global__ void __launch_bounds__(256) k_rowk(
        const float* __restrict__ S, const float* __restrict__ T) {
    __shared__ float red[14][9];
    __shared__ float redd2[8];
    int n = blockIdx.y;
    int c0 = blockIdx.x * 2;
    int tid = threadIdx.x, lane = tid & 31, warp = tid >> 5;
    float a_chs[2] = {0.f, 0.f};
    float a_cht[2] = {0.f, 0.f};
    float a_cxs[2] = {0.f, 0.f};
    float a_cxt[2] = {0.f, 0.f};
    float a_rd [2] = {0.f, 0.f};
    float a_fg [2] = {0.f, 0.f};
    float a_bg [2] = {0.f, 0.f};
    float d2a = 0.f;
    const uint4* W4 = (const uint4*)(g_smwh + n * HWSZ);
    const float* Sb = S + ((size_t)n * CC + c0) * HWSZ;
    const float* Tb = T + ((size_t)n * CC + c0) * HWSZ;
    int pbase = warp * 2048;

#pragma unroll 1
    for (int g = 0; g < 16; g++) {
        int p = pbase + g * 128 + lane * 4;
        uint4 wa = W4[p >> 1];
        uint4 wb = W4[(p >> 1) + 1];
        float4 sv[2], tv[2];
#pragma unroll
        for (int c = 0; c < 2; c++) {
            sv[c] = *(const float4*)(Sb + (size_t)c * HWSZ + p);
            tv[c] = *(const float4*)(Tb + (size_t)c * HWSZ + p);
        }
        float2 a0 = h2f(wa.x), b0 = h2f(wa.y);
        float2 a1 = h2f(wa.z), b1 = h2f(wa.w);
        float2 a2 = h2f(wb.x), b2 = h2f(wb.y);
        float2 a3 = h2f(wb.z), b3 = h2f(wb.w);
        float4 wv[4];
        wv[0] = make_float4(a0.x, a0.y, b0.x, b0.y);
        wv[1] = make_float4(a1.x, a1.y, b1.x, b1.y);
        wv[2] = make_float4(a2.x, a2.y, b2.x, b2.y);
        wv[3] = make_float4(a3.x, a3.y, b3.x, b3.y);
#pragma unroll
        for (int c = 0; c < 2; c++) {
            float4 s = sv[c], t = tv[c];
            a_chs[c] += (fabsf(s.x) + fabsf(s.y)) + (fabsf(s.z) + fabsf(s.w));
            a_cht[c] += (fabsf(t.x) + fabsf(t.y)) + (fabsf(t.z) + fabsf(t.w));
            a_cxs[c] = fmaf(s.x, wv[0].x, fmaf(s.y, wv[1].x, fmaf(s.z, wv[2].x, fmaf(s.w, wv[3].x, a_cxs[c]))));
            a_cxt[c] = fmaf(t.x, wv[0].y, fmaf(t.y, wv[1].y, fmaf(t.z, wv[2].y, fmaf(t.w, wv[3].y, a_cxt[c]))));
            float dx = s.x - t.x, dy = s.y - t.y, dz = s.z - t.z, dw = s.w - t.w;
            a_rd[c] += (dx + dy) + (dz + dw);
            float ex = dx * dx, ey = dy * dy, ez = dz * dz, ew = dw * dw;
            d2a += (ex + ey) + (ez + ew);
            a_fg[c] = fmaf(ex, wv[0].z, fmaf(ey, wv[1].z, fmaf(ez, wv[2].z, fmaf(ew, wv[3].z, a_fg[c]))));
            a_bg[c] = fmaf(ex, wv[0].w, fmaf(ey, wv[1].w, fmaf(ez, wv[2].w, fmaf(ew, wv[3].w, a_bg[c]))));
        }
    }
#pragma unroll
    for (int c = 0; c < 2; c++) {
        float v;
        v = warpsum(a_chs[c]); if (lane == 0) red[0 * 2 + c][warp] = v;
        v = warpsum(a_cht[c]); if (lane == 0) red[1 * 2 + c][warp] = v;
        v = warpsum(a_cxs[c]); if (lane == 0) red[2 * 2 + c][warp] = v;
        v = warpsum(a_cxt[c]); if (lane == 0) red[3 * 2 + c][warp] = v;
        v = warpsum(a_rd [c]); if (lane == 0) red[4 * 2 + c][warp] = v;
        v = warpsum(a_fg [c]); if (lane == 0) red[5 * 2 + c][warp] = v;
        v = warpsum(a_bg [c]); if (lane == 0) red[6 * 2 + c][warp] = v;
    }
    d2a = warpsum(d2a);
    if (lane == 0) redd2[warp] = d2a;
    __syncthreads();
    if (tid < 14) {
        float v = 0.f;
#pragma unroll
        for (int w = 0; w < 8; w++) v += red[tid][w];
        int arr = tid >> 1, c = tid & 1;
        int o = n * CC + c0 + c;
        switch (arr) {
            case 0: g_ch_s [o] = v; break;
            case 1: g_ch_t [o] = v; break;
            case 2: g_ctx_s[o] = v * (1.0f / SM_SC); break;
            case 3: g_ctx_t[o] = v * (1.0f / SM_SC); break;
            case 4: g_rowd [o] = v; break;
            case 5: g_fgrow[o] = v * (1.0f / FG_SC); break;
            case 6: g_bgrow[o] = v * (1.0f / BG_SC); break;
        }
    }
    if (tid == 14) {
        float v = 0.f;
#pragma unroll
        for (int w = 0; w < 8; w++) v += redd2[w];
        atomicAdd(&g_d2sum, v);
    }
}

// ---------------- k_final: channel softmax terms + MLPs (512 threads) --------
// grid NN, block 512 (16 warps)
__global__ void __launch_bounds__(512) k_final(
        const float* __restrict__ w1s, const float* __restrict__ b1s,
        const float* __restrict__ gs,  const float* __restrict__ bes,
        const float* __restrict__ w2s, const float* __restrict__ b2s,
        const float* __restrict__ w1t, const float* __restrict__ b1t,
        const float* __restrict__ gtl, const float* __restrict__ bet,
        const float* __restrict__ w2t, const float* __restrict__ b2t) {
    __shared__ float sctxs[CC], sctxt[CC];
    __shared__ float sy[256];
    __shared__ float sadd[512];
    __shared__ float swsum[8], swsq[8];
    __shared__ float sbuf[32];
    int n = blockIdx.x;
    int tid = threadIdx.x, lane = tid & 31, warp = tid >> 5;
    bool act = (tid < 256);

    // channel softmaxes + Ct-weighted fg/bg + mask term (channels on tid<256)
    {
        const float sc = 1.0f / ((float)HWSZ * TEMP);
        float es = act ? __expf(g_ch_s[n * CC + tid] * sc) : 0.f;
        float et = act ? __expf(g_ch_t[n * CC + tid] * sc) : 0.f;
        float ss = blocksum(es, sbuf);
        float st = blocksum(et, sbuf);
        float Cs = (float)CC * es / ss;
        float Ct = (float)CC * et / st;
        float fw = act ? g_fgrow[n * CC + tid] : 0.f;
        float bw = act ? g_bgrow[n * CC + tid] : 0.f;
        float d   = blocksum(fabsf(Cs - Ct), sbuf);
        float fgp = blocksum(Ct * fw, sbuf);
        float bgp = blocksum(Ct * bw, sbuf);
        if (tid == 0) {
            atomicAdd(&g_maskloss, d);
            atomicAdd(&g_fgsum, fgp);
            atomicAdd(&g_bgsum, bgp);
        }
    }

    if (act) {
        sctxs[tid] = g_ctx_s[n * CC + tid];
        sctxt[tid] = g_ctx_t[n * CC + tid];
    }
    __syncthreads();

    // layer 1: 256 outputs over 16 warps (16 each)
#pragma unroll 1
    for (int i = 0; i < 16; i++) {
        int oidx = warp * 16 + i;
        bool isT = (oidx >= 128);
        int j = oidx & 127;
        const float* row = (isT ? w1t : w1s) + (size_t)j * CC;
        const float* cx  = isT ? sctxt : sctxs;
        float acc = 0.f;
#pragma unroll
        for (int c = 0; c < CC; c += 32)
            acc = fmaf(row[c + lane], cx[c + lane], acc);
        acc = warpsum(acc);
        if (lane == 0) sy[oidx] = acc + (isT ? b1t : b1s)[j];
    }
    __syncthreads();

    // LayerNorm + ReLU (entries on tid<256; warps 0..7)
    {
        float y = act ? sy[tid] : 0.f;
        float v = warpsum(y), v2 = warpsum(y * y);
        if (lane == 0 && warp < 8) { swsum[warp] = v; swsq[warp] = v2; }
        __syncthreads();
        if (act) {
            int j = tid & 127;
            bool isT = (tid >= 128);
            int h0 = isT ? 4 : 0;
            float mean = (swsum[h0] + swsum[h0 + 1] + swsum[h0 + 2] + swsum[h0 + 3]) * (1.0f / 128.0f);
            float msq  = (swsq[h0] + swsq[h0 + 1] + swsq[h0 + 2] + swsq[h0 + 3]) * (1.0f / 128.0f);
            float var = msq - mean * mean;
            y = (y - mean) * rsqrtf(var + LN_EPS) * (isT ? gtl : gs)[j] + (isT ? bet : bes)[j];
            sy[tid] = fmaxf(y, 0.f);
        }
    }
    __syncthreads();

    // layer 2: 512 outputs over 16 warps (32 each)
#pragma unroll 1
    for (int i = 0; i < 32; i++) {
        int oidx = warp * 32 + i;
        bool isT = (oidx >= 256);
        int c = oidx & 255;
        const float* row = (isT ? w2t : w2s) + (size_t)c * 128;
        int base = isT ? 128 : 0;
        float acc = 0.f;
#pragma unroll
        for (int j = 0; j < 128; j += 32)
            acc = fmaf(row[j + lane], sy[base + j + lane], acc);
        acc = warpsum(acc);
        if (lane == 0) sadd[oidx] = acc + (isT ? b2t : b2s)[c];
    }
    __syncthreads();

    // delta terms (tid<256)
    {
        float delta = act ? (sadd[tid] - sadd[256 + tid]) : 0.f;
        float rd = act ? g_rowd[n * CC + tid] : 0.f;
        float ax = delta * rd;
        float ad = delta * delta;
        ax = blocksum(ax, sbuf);
        ad = blocksum(ad, sbuf);
        if (tid == 0) {
            atomicAdd(&g_accx, ax);
            atomicAdd(&g_accd, ad);
        }
    }
}

// ---------------- k_out ------------------------------------------------------
__global__ void __launch_bounds__(32) k_out(float* __restrict__ out) {
    if (threadIdx.x == 0) {
        float rela = g_d2sum + 2.0f * g_accx + (float)HWSZ * g_accd;
        float loss = (ALPHA * g_fgsum + BETA * g_bgsum + GAMMA * g_maskloss + LAMB * rela)
                     * (1.0f / (float)NN);
        out[0] = loss;
    }
}

// ---------------- launch ----------------
extern "C" void kernel_launch(void* const* d_in, const int* in_sizes, int n_in,
                              void* d_out, int out_size) {
    const float* S   = (const float*)d_in[0];
    const float* T   = (const float*)d_in[1];
    const float* gt  = (const float*)d_in[2];
    const float* wms = (const float*)d_in[3];
    const float* wmt = (const float*)d_in[5];
    const float* w1s = (const float*)d_in[7];
    const float* b1s = (const float*)d_in[8];
    const float* gs  = (const float*)d_in[9];
    const float* bes = (const float*)d_in[10];
    const float* w2s = (const float*)d_in[11];
    const float* b2s = (const float*)d_in[12];
    const float* w1t = (const float*)d_in[13];
    const float* b1t = (const float*)d_in[14];
    const float* gtl = (const float*)d_in[15];
    const float* bet = (const float*)d_in[16];
    const float* w2t = (const float*)d_in[17];
    const float* b2t = (const float*)d_in[18];

    k_pass1<<<dim3(32, NN), 512>>>(S, T, wms, wmt, gt);     // 1
    k_wgt  <<<dim3(64, NN), 256>>>();                       // 2
    k_rowk <<<dim3(CC / 2, NN), 256>>>(S, T);               // 3
    k_final<<<NN, 512>>>(w1s, b1s, gs, bes, w2s, b2s,
                         w1t, b1t, gtl, bet, w2t, b2t);     // 4  <-- profiled slot
    k_out  <<<1, 32>>>((float*)d_out);                      // 5
}

// round 17
// speedup vs baseline: 1.1767x; 1.1767x over previous
#include <cuda_runtime.h>
#include <cuda_fp16.h>

#define NN   8
#define CC   256
#define HC   128
#define HH   128
#define WW   128
#define HWSZ 16384
#define NBOX 20
#define TEMP     0.5f
#define INVTEMP  2.0f
#define ALPHA    1e-3f
#define BETA     5e-4f
#define GAMMA    1e-3f
#define LAMB     5e-6f
#define IMGF     1024.0f
#define LN_EPS   1e-5f

#define SM_SC  16384.0f
#define FG_SC  64.0f
#define BG_SC  16384.0f

// ---------------- scratch ----------------
__device__ float4 g_pp [NN * HWSZ];
__device__ float  g_mfg[NN * HWSZ];
__device__ uint2  g_smwh[NN * HWSZ];
__device__ float g_ch_s [NN * CC];
__device__ float g_ch_t [NN * CC];
__device__ float g_ctx_s[NN * CC];
__device__ float g_ctx_t[NN * CC];
__device__ float g_rowd [NN * CC];
__device__ float g_fgrow[NN * CC];
__device__ float g_bgrow[NN * CC];
__device__ float g_denp[NN][5][32];
__device__ float g_y [NN * 256];      // layer1 raw outputs (128 s + 128 t)
__device__ float g_yr[NN * 256];      // layer1 after LN+ReLU
__device__ float g_fgsum, g_bgsum, g_d2sum, g_maskloss;
__device__ float g_accx, g_accd;

// ---------------- helpers ----------------
__device__ __forceinline__ float warpsum(float v) {
#pragma unroll
    for (int o = 16; o > 0; o >>= 1) v += __shfl_xor_sync(0xffffffffu, v, o);
    return v;
}
__device__ __forceinline__ float blocksum(float v, float* sbuf) {
    int tid = threadIdx.x, lane = tid & 31, warp = tid >> 5;
    int nw = blockDim.x >> 5;
    v = warpsum(v);
    if (lane == 0) sbuf[warp] = v;
    __syncthreads();
    if (warp == 0) {
        float r = (lane < nw) ? sbuf[lane] : 0.0f;
        r = warpsum(r);
        if (lane == 0) sbuf[0] = r;
    }
    __syncthreads();
    float r = sbuf[0];
    __syncthreads();
    return r;
}
__device__ __forceinline__ float2 h2f(unsigned u) {
    __half2 h = *reinterpret_cast<__half2*>(&u);
    return __half22float2(h);
}

// ---------------- pass1: mask + per-pixel sums + denominators (fused) --------
// grid (32, NN), block 512: lower half = channels 0..127, upper = 128..255
__global__ void __launch_bounds__(512) k_pass1(
        const float* __restrict__ S, const float* __restrict__ T,
        const float* __restrict__ wms, const float* __restrict__ wmt,
        const float* __restrict__ gt) {
    __shared__ float sws[CC], swt[CC];
    __shared__ float bhmin[NBOX], bhmax[NBOX], bwmin[NBOX], bwmax[NBOX], barea[NBOX];
    __shared__ float4 xch0[256], xch1[256];
    __shared__ float sbuf[32];
    int tid = threadIdx.x;
    int n = blockIdx.y;
    int half = tid >> 8;
    int lt = tid & 255;
    int c0 = half * HC;

    if (blockIdx.x == 0 && n == 0 && tid == 0) {
        g_fgsum = 0.f; g_bgsum = 0.f; g_d2sum = 0.f; g_maskloss = 0.f;
        g_accx = 0.f; g_accd = 0.f;
    }
    if (tid < CC) { sws[tid] = wms[tid]; swt[tid] = wmt[tid]; }
    if (tid < NBOX) {
        const float* b = gt + ((size_t)n * NBOX + tid) * 4;
        float wmin = floorf(b[0] * ((float)WW / IMGF));
        float hmin = floorf(b[1] * ((float)HH / IMGF));
        float wmax = ceilf (b[2] * ((float)WW / IMGF));
        float hmax = ceilf (b[3] * ((float)HH / IMGF));
        bhmin[tid] = hmin; bhmax[tid] = hmax;
        bwmin[tid] = wmin; bwmax[tid] = wmax;
        barea[tid] = 1.0f / ((hmax + 1.0f - hmin) * (wmax + 1.0f - wmin));
    }
    __syncthreads();

    int p = blockIdx.x * 512 + lt * 2;
    int o = n * HWSZ + p;

    const float2* Sp = (const float2*)(S + ((size_t)n * CC + c0) * HWSZ + p);
    const float2* Tp = (const float2*)(T + ((size_t)n * CC + c0) * HWSZ + p);
    float2 fs = make_float2(0.f, 0.f), ft = fs, cs = fs, ct = fs;
#pragma unroll 1
    for (int cg = 0; cg < HC; cg += 8) {
        float2 sv[8], tv[8];
#pragma unroll
        for (int u = 0; u < 8; u++) {
            sv[u] = Sp[(size_t)(cg + u) * (HWSZ / 2)];
            tv[u] = Tp[(size_t)(cg + u) * (HWSZ / 2)];
        }
#pragma unroll
        for (int u = 0; u < 8; u++) {
            float2 s = sv[u], t = tv[u];
            fs.x += fabsf(s.x); fs.y += fabsf(s.y);
            ft.x += fabsf(t.x); ft.y += fabsf(t.y);
            float ws = sws[c0 + cg + u], wt = swt[c0 + cg + u];
            cs.x = fmaf(s.x, ws, cs.x); cs.y = fmaf(s.y, ws, cs.y);
            ct.x = fmaf(t.x, wt, ct.x); ct.y = fmaf(t.y, wt, ct.y);
        }
    }
    if (half == 1) {
        xch0[lt] = make_float4(fs.x, ft.x, cs.x, ct.x);
        xch1[lt] = make_float4(fs.y, ft.y, cs.y, ct.y);
    }
    __syncthreads();

    float s0 = 0.f, s1 = 0.f, s2 = 0.f, s3 = 0.f, bgp = 0.f;
    if (half == 0) {
        float4 u0 = xch0[lt], u1 = xch1[lt];
        float fs0 = fs.x + u0.x, ft0 = ft.x + u0.y, cs0 = cs.x + u0.z, ct0 = ct.x + u0.w;
        float fs1 = fs.y + u1.x, ft1 = ft.y + u1.y, cs1 = cs.y + u1.z, ct1 = ct.y + u1.w;

        float h0 = (float)(p >> 7), w0 = (float)(p & 127);
        float h1 = (float)((p + 1) >> 7), w1 = (float)((p + 1) & 127);
        float mfg0 = 0.f, mfg1 = 0.f;
#pragma unroll 1
        for (int b = 0; b < NBOX; b++) {
            float hm = bhmin[b], hM = bhmax[b], wm = bwmin[b], wM = bwmax[b], ar = barea[b];
            if (h0 >= hm && h0 <= hM && w0 >= wm && w0 <= wM) mfg0 = fmaxf(mfg0, ar);
            if (h1 >= hm && h1 <= hM && w1 >= wm && w1 <= wM) mfg1 = fmaxf(mfg1, ar);
        }
        g_mfg[o] = mfg0; g_mfg[o + 1] = mfg1;
        g_pp[o]     = make_float4(fs0, ft0, cs0, ct0);
        g_pp[o + 1] = make_float4(fs1, ft1, cs1, ct1);

        const float sc = INVTEMP / (float)CC;
        s0 = __expf(fs0 * sc) + __expf(fs1 * sc);
        s1 = __expf(ft0 * sc) + __expf(ft1 * sc);
        s2 = __expf(cs0) + __expf(cs1);
        s3 = __expf(ct0) + __expf(ct1);
        bgp = (mfg0 == 0.f ? 1.f : 0.f) + (mfg1 == 0.f ? 1.f : 0.f);
    }
    s0 = blocksum(s0, sbuf); s1 = blocksum(s1, sbuf);
    s2 = blocksum(s2, sbuf); s3 = blocksum(s3, sbuf);
    bgp = blocksum(bgp, sbuf);
    if (tid == 0) {
        g_denp[n][0][blockIdx.x] = s0;
        g_denp[n][1][blockIdx.x] = s1;
        g_denp[n][2][blockIdx.x] = s2;
        g_denp[n][3][blockIdx.x] = s3;
        g_denp[n][4][blockIdx.x] = bgp;
    }
}

// ---------------- k_wgt: fp16-packed weights + |Ss-St| term ------------------
// grid (64, NN), block 256
__global__ void __launch_bounds__(256) k_wgt() {
    __shared__ float sbuf[32];
    __shared__ float sden[5];
    int n = blockIdx.y, tid = threadIdx.x;
    int lane = tid & 31, warp = tid >> 5;
    if (warp == 0) {
#pragma unroll
        for (int j = 0; j < 5; j++) {
            float v = warpsum(g_denp[n][j][lane]);
            if (lane == 0) sden[j] = v;
        }
    }
    __syncthreads();
    int o = n * HWSZ + blockIdx.x * 256 + tid;
    const float sc = INVTEMP / (float)CC;
    float r0 = 1.0f / sden[0];
    float r1 = 1.0f / sden[1];
    float r2 = 1.0f / sden[2];
    float r3 = 1.0f / sden[3];
    float bgc = sden[4];
    float invbg = (bgc > 0.f) ? (1.0f / bgc) : 0.f;
    float4 a = g_pp[o];
    float mfg = g_mfg[o];
    float Ss  = (float)HWSZ * __expf(a.x * sc) * r0;
    float St  = (float)HWSZ * __expf(a.y * sc) * r1;
    float sms = __expf(a.z) * r2;
    float smt = __expf(a.w) * r3;
    float mbg = (mfg > 0.f) ? 0.f : invbg;
    __half2 hA = __floats2half2_rn(sms * SM_SC, smt * SM_SC);
    __half2 hB = __floats2half2_rn(St * mfg * FG_SC, St * mbg * BG_SC);
    uint2 v;
    v.x = *reinterpret_cast<unsigned*>(&hA);
    v.y = *reinterpret_cast<unsigned*>(&hB);
    g_smwh[o] = v;
    float sd = blocksum(fabsf(Ss - St), sbuf);
    if (tid == 0) atomicAdd(&g_maskloss, sd);
}

// ---------------- k_rowk: second stream -> all per-channel reductions --------
// grid (CC/2, NN), block 256, 2 channels/block, fp16 weights
__global__ void __launch_bounds__(256) k_rowk(
        const float* __restrict__ S, const float* __restrict__ T) {
    __shared__ float red[14][9];
    __shared__ float redd2[8];
    int n = blockIdx.y;
    int c0 = blockIdx.x * 2;
    int tid = threadIdx.x, lane = tid & 31, warp = tid >> 5;
    float a_chs[2] = {0.f, 0.f};
    float a_cht[2] = {0.f, 0.f};
    float a_cxs[2] = {0.f, 0.f};
    float a_cxt[2] = {0.f, 0.f};
    float a_rd [2] = {0.f, 0.f};
    float a_fg [2] = {0.f, 0.f};
    float a_bg [2] = {0.f, 0.f};
    float d2a = 0.f;
    const uint4* W4 = (const uint4*)(g_smwh + n * HWSZ);
    const float* Sb = S + ((size_t)n * CC + c0) * HWSZ;
    const float* Tb = T + ((size_t)n * CC + c0) * HWSZ;
    int pbase = warp * 2048;

#pragma unroll 1
    for (int g = 0; g < 16; g++) {
        int p = pbase + g * 128 + lane * 4;
        uint4 wa = W4[p >> 1];
        uint4 wb = W4[(p >> 1) + 1];
        float4 sv[2], tv[2];
#pragma unroll
        for (int c = 0; c < 2; c++) {
            sv[c] = *(const float4*)(Sb + (size_t)c * HWSZ + p);
            tv[c] = *(const float4*)(Tb + (size_t)c * HWSZ + p);
        }
        float2 a0 = h2f(wa.x), b0 = h2f(wa.y);
        float2 a1 = h2f(wa.z), b1 = h2f(wa.w);
        float2 a2 = h2f(wb.x), b2 = h2f(wb.y);
        float2 a3 = h2f(wb.z), b3 = h2f(wb.w);
        float4 wv[4];
        wv[0] = make_float4(a0.x, a0.y, b0.x, b0.y);
        wv[1] = make_float4(a1.x, a1.y, b1.x, b1.y);
        wv[2] = make_float4(a2.x, a2.y, b2.x, b2.y);
        wv[3] = make_float4(a3.x, a3.y, b3.x, b3.y);
#pragma unroll
        for (int c = 0; c < 2; c++) {
            float4 s = sv[c], t = tv[c];
            a_chs[c] += (fabsf(s.x) + fabsf(s.y)) + (fabsf(s.z) + fabsf(s.w));
            a_cht[c] += (fabsf(t.x) + fabsf(t.y)) + (fabsf(t.z) + fabsf(t.w));
            a_cxs[c] = fmaf(s.x, wv[0].x, fmaf(s.y, wv[1].x, fmaf(s.z, wv[2].x, fmaf(s.w, wv[3].x, a_cxs[c]))));
            a_cxt[c] = fmaf(t.x, wv[0].y, fmaf(t.y, wv[1].y, fmaf(t.z, wv[2].y, fmaf(t.w, wv[3].y, a_cxt[c]))));
            float dx = s.x - t.x, dy = s.y - t.y, dz = s.z - t.z, dw = s.w - t.w;
            a_rd[c] += (dx + dy) + (dz + dw);
            float ex = dx * dx, ey = dy * dy, ez = dz * dz, ew = dw * dw;
            d2a += (ex + ey) + (ez + ew);
            a_fg[c] = fmaf(ex, wv[0].z, fmaf(ey, wv[1].z, fmaf(ez, wv[2].z, fmaf(ew, wv[3].z, a_fg[c]))));
            a_bg[c] = fmaf(ex, wv[0].w, fmaf(ey, wv[1].w, fmaf(ez, wv[2].w, fmaf(ew, wv[3].w, a_bg[c]))));
        }
    }
#pragma unroll
    for (int c = 0; c < 2; c++) {
        float v;
        v = warpsum(a_chs[c]); if (lane == 0) red[0 * 2 + c][warp] = v;
        v = warpsum(a_cht[c]); if (lane == 0) red[1 * 2 + c][warp] = v;
        v = warpsum(a_cxs[c]); if (lane == 0) red[2 * 2 + c][warp] = v;
        v = warpsum(a_cxt[c]); if (lane == 0) red[3 * 2 + c][warp] = v;
        v = warpsum(a_rd [c]); if (lane == 0) red[4 * 2 + c][warp] = v;
        v = warpsum(a_fg [c]); if (lane == 0) red[5 * 2 + c][warp] = v;
        v = warpsum(a_bg [c]); if (lane == 0) red[6 * 2 + c][warp] = v;
    }
    d2a = warpsum(d2a);
    if (lane == 0) redd2[warp] = d2a;
    __syncthreads();
    if (tid < 14) {
        float v = 0.f;
#pragma unroll
        for (int w = 0; w < 8; w++) v += red[tid][w];
        int arr = tid >> 1, c = tid & 1;
        int o = n * CC + c0 + c;
        switch (arr) {
            case 0: g_ch_s [o] = v; break;
            case 1: g_ch_t [o] = v; break;
            case 2: g_ctx_s[o] = v * (1.0f / SM_SC); break;
            case 3: g_ctx_t[o] = v * (1.0f / SM_SC); break;
            case 4: g_rowd [o] = v; break;
            case 5: g_fgrow[o] = v * (1.0f / FG_SC); break;
            case 6: g_bgrow[o] = v * (1.0f / BG_SC); break;
        }
    }
    if (tid == 14) {
        float v = 0.f;
#pragma unroll
        for (int w = 0; w < 8; w++) v += redd2[w];
        atomicAdd(&g_d2sum, v);
    }
}

// ---------------- kA: MLP layer1 (wide) --------------------------------------
// grid (8, NN), block 256 (8 warps); warp computes 4 of 256 outputs
__global__ void __launch_bounds__(256) k_mlp1(
        const float* __restrict__ w1s, const float* __restrict__ b1s,
        const float* __restrict__ w1t, const float* __restrict__ b1t) {
    int n = blockIdx.y;
    int tid = threadIdx.x, lane = tid & 31, warp = tid >> 5;
#pragma unroll 1
    for (int i = 0; i < 4; i++) {
        int oidx = blockIdx.x * 32 + warp * 4 + i;
        bool isT = (oidx >= 128);
        int j = oidx & 127;
        const float* row = (isT ? w1t : w1s) + (size_t)j * CC;
        const float* cx  = (isT ? g_ctx_t : g_ctx_s) + n * CC;
        float acc = 0.f;
#pragma unroll
        for (int c = 0; c < CC; c += 32)
            acc = fmaf(row[c + lane], cx[c + lane], acc);
        acc = warpsum(acc);
        if (lane == 0) g_y[n * 256 + oidx] = acc + (isT ? b1t : b1s)[j];
    }
}

// ---------------- kB: channel softmax terms + LayerNorm + ReLU ---------------
// grid NN, block 256 (thread = channel / layer1 output)
__global__ void __launch_bounds__(256) k_lnact(
        const float* __restrict__ gs,  const float* __restrict__ bes,
        const float* __restrict__ gtl, const float* __restrict__ bet) {
    __shared__ float sbuf[32];
    __shared__ float swsum[8], swsq[8];
    int n = blockIdx.x, tid = threadIdx.x;
    int lane = tid & 31, warp = tid >> 5;

    // channel softmaxes + Ct-weighted fg/bg + mask term
    {
        const float sc = 1.0f / ((float)HWSZ * TEMP);
        float es = __expf(g_ch_s[n * CC + tid] * sc);
        float et = __expf(g_ch_t[n * CC + tid] * sc);
        float ss = blocksum(es, sbuf);
        float st = blocksum(et, sbuf);
        float Cs = (float)CC * es / ss;
        float Ct = (float)CC * et / st;
        float d   = blocksum(fabsf(Cs - Ct), sbuf);
        float fgp = blocksum(Ct * g_fgrow[n * CC + tid], sbuf);
        float bgp = blocksum(Ct * g_bgrow[n * CC + tid], sbuf);
        if (tid == 0) {
            atomicAdd(&g_maskloss, d);
            atomicAdd(&g_fgsum, fgp);
            atomicAdd(&g_bgsum, bgp);
        }
    }

    // LayerNorm + ReLU on g_y (branch = 128 consecutive entries = warps 0-3 / 4-7)
    float y = g_y[n * 256 + tid];
    float v = warpsum(y), v2 = warpsum(y * y);
    if (lane == 0) { swsum[warp] = v; swsq[warp] = v2; }
    __syncthreads();
    int j = tid & 127;
    bool isT = (tid >= 128);
    int h0 = isT ? 4 : 0;
    float mean = (swsum[h0] + swsum[h0 + 1] + swsum[h0 + 2] + swsum[h0 + 3]) * (1.0f / 128.0f);
    float msq  = (swsq[h0] + swsq[h0 + 1] + swsq[h0 + 2] + swsq[h0 + 3]) * (1.0f / 128.0f);
    float var = msq - mean * mean;
    y = (y - mean) * rsqrtf(var + LN_EPS) * (isT ? gtl : gs)[j] + (isT ? bet : bes)[j];
    g_yr[n * 256 + tid] = fmaxf(y, 0.f);
}

// ---------------- kC: MLP layer2 + delta terms (wide) ------------------------
// grid (8, NN), block 256 (8 warps); block owns 32 channels x both branches
__global__ void __launch_bounds__(256) k_mlp2(
        const float* __restrict__ w2s, const float* __restrict__ b2s,
        const float* __restrict__ w2t, const float* __restrict__ b2t) {
    __shared__ float sadd[2][32];
    int n = blockIdx.y;
    int tid = threadIdx.x, lane = tid & 31, warp = tid >> 5;
#pragma unroll 1
    for (int i = 0; i < 8; i++) {
        int idx = warp * 8 + i;          // 0..63
        int branch = idx >> 5;           // 0 = s, 1 = t
        int cl = idx & 31;
        int c = blockIdx.x * 32 + cl;
        const float* row = (branch ? w2t : w2s) + (size_t)c * 128;
        const float* vec = g_yr + n * 256 + branch * 128;
        float acc = 0.f;
#pragma unroll
        for (int j = 0; j < 128; j += 32)
            acc = fmaf(row[j + lane], vec[j + lane], acc);
        acc = warpsum(acc);
        if (lane == 0) sadd[branch][cl] = acc + (branch ? b2t : b2s)[c];
    }
    __syncthreads();
    if (warp == 0) {
        int c = blockIdx.x * 32 + lane;
        float delta = sadd[0][lane] - sadd[1][lane];
        float ax = warpsum(delta * g_rowd[n * CC + c]);
        float ad = warpsum(delta * delta);
        if (lane == 0) {
            atomicAdd(&g_accx, ax);
            atomicAdd(&g_accd, ad);
        }
    }
}

// ---------------- k_out ------------------------------------------------------
__global__ void __launch_bounds__(32) k_out(float* __restrict__ out) {
    if (threadIdx.x == 0) {
        float rela = g_d2sum + 2.0f * g_accx + (float)HWSZ * g_accd;
        float loss = (ALPHA * g_fgsum + BETA * g_bgsum + GAMMA * g_maskloss + LAMB * rela)
                     * (1.0f / (float)NN);
        out[0] = loss;
    }
}

// ---------------- launch ----------------
extern "C" void kernel_launch(void* const* d_in, const int* in_sizes, int n_in,
                              void* d_out, int out_size) {
    const float* S   = (const float*)d_in[0];
    const float* T   = (const float*)d_in[1];
    const float* gt  = (const float*)d_in[2];
    const float* wms = (const float*)d_in[3];
    const float* wmt = (const float*)d_in[5];
    const float* w1s = (const float*)d_in[7];
    const float* b1s = (const float*)d_in[8];
    const float* gs  = (const float*)d_in[9];
    const float* bes = (const float*)d_in[10];
    const float* w2s = (const float*)d_in[11];
    const float* b2s = (const float*)d_in[12];
    const float* w1t = (const float*)d_in[13];
    const float* b1t = (const float*)d_in[14];
    const float* gtl = (const float*)d_in[15];
    const float* bet = (const float*)d_in[16];
    const float* w2t = (const float*)d_in[17];
    const float* b2t = (const float*)d_in[18];

    k_pass1<<<dim3(32, NN), 512>>>(S, T, wms, wmt, gt);   // 1
    k_wgt  <<<dim3(64, NN), 256>>>();                     // 2
    k_rowk <<<dim3(CC / 2, NN), 256>>>(S, T);             // 3
    k_mlp1 <<<dim3(8, NN), 256>>>(w1s, b1s, w1t, b1t);    // 4  <-- profiled slot
    k_lnact<<<NN, 256>>>(gs, bes, gtl, bet);              // 5
    k_mlp2 <<<dim3(8, NN), 256>>>(w2s, b2s, w2t, b2t);    // 6
    k_out  <<<1, 32>>>((float*)d_out);                    // 7
}